// round 1
// baseline (speedup 1.0000x reference)
#include <cuda_runtime.h>
#include <cuda_bf16.h>
#include <math.h>
#include <stdint.h>

// Problem constants
#define QLEN  2048
#define BSZ   2
#define NH    16
#define DH    64
#define DM    1024
#define KLEN  2048
#define RLEN  2048
#define SCALE 0.125f   // 1/sqrt(64)

// ---------------- scratch (device globals; no allocations allowed) ----------
__device__ float g_Qb[(size_t)BSZ * NH * QLEN * DH];   // Q + r_r_bias, (b,n,q,d)
__device__ float g_K [(size_t)BSZ * NH * KLEN * DH];   // (b,n,k,d)
__device__ float g_V [(size_t)BSZ * NH * KLEN * DH];   // (b,n,k,d)
__device__ float g_Rk[(size_t)NH * RLEN * DH];         // (n,r,d)
__device__ float g_BD[(size_t)BSZ * NH * QLEN * RLEN]; // raw BD, (b,n,q,r)  536MB
__device__ float g_AV[(size_t)QLEN * BSZ * DM];        // attn_vec, (q,b,n*d)
__device__ int   g_mask_mode;                          // 0=int32, 1=float32, 2=byte/bool

// ---------------- mask dtype detection --------------------------------------
// Reads only first 4096 bytes (valid for bool[4096], int32[4096], float[4096]).
__global__ void detect_mask_kernel(const unsigned char* __restrict__ m) {
    __shared__ int cnt[4];
    if (threadIdx.x < 4) cnt[threadIdx.x] = 0;
    __syncthreads();
    for (int i = threadIdx.x; i < 4096; i += blockDim.x)
        if (m[i]) atomicAdd(&cnt[i & 3], 1);
    __syncthreads();
    if (threadIdx.x == 0) {
        int mode;
        if (cnt[1] == 0 && cnt[2] == 0 && cnt[3] == 0) mode = 0;      // int32: only byte0 set
        else if (cnt[0] == 0 && cnt[1] == 0)           mode = 1;      // float: bytes 2,3 (0x80 0x3f)
        else                                           mode = 2;      // 1-byte bool
        g_mask_mode = mode;
    }
}

// ---------------- GEMM 1: heads = w @ qkv_w, scatter to Qb/K/V --------------
// A: (4096 x 1024) row-major (w viewed flat, row = q*2+b). B: (1024 x 3072).
__global__ __launch_bounds__(256)
void gemm_qkv_kernel(const float* __restrict__ A, const float* __restrict__ B,
                     const float* __restrict__ rbias) {
    const int K = DM, N = 3 * NH * DH;  // 1024, 3072
    __shared__ float As[8][128];
    __shared__ float Bs[8][128];
    int tid = threadIdx.x;
    int tx = tid & 15, ty = tid >> 4;
    int row0 = blockIdx.y * 128, col0 = blockIdx.x * 128;
    float acc[8][8] = {};
    int ar = tid >> 1, ac = (tid & 1) * 4;
    int br = tid >> 5, bc = (tid & 31) * 4;
    for (int k0 = 0; k0 < K; k0 += 8) {
        float4 av = *(const float4*)&A[(size_t)(row0 + ar) * K + k0 + ac];
        As[ac + 0][ar] = av.x; As[ac + 1][ar] = av.y;
        As[ac + 2][ar] = av.z; As[ac + 3][ar] = av.w;
        *(float4*)&Bs[br][bc] = *(const float4*)&B[(size_t)(k0 + br) * N + col0 + bc];
        __syncthreads();
#pragma unroll
        for (int kk = 0; kk < 8; kk++) {
            float a[8], b[8];
#pragma unroll
            for (int i = 0; i < 8; i++) a[i] = As[kk][ty * 8 + i];
#pragma unroll
            for (int j = 0; j < 8; j++) b[j] = Bs[kk][tx * 8 + j];
#pragma unroll
            for (int i = 0; i < 8; i++)
#pragma unroll
                for (int j = 0; j < 8; j++) acc[i][j] += a[i] * b[j];
        }
        __syncthreads();
    }
#pragma unroll
    for (int i = 0; i < 8; i++) {
        int m = row0 + ty * 8 + i;
        int q = m >> 1, b = m & 1;
#pragma unroll
        for (int j = 0; j < 8; j++) {
            int c = col0 + tx * 8 + j;
            int sec = c >> 10;            // /1024: 0=Q,1=K,2=V
            int h = (c & 1023) >> 6;
            int d = c & 63;
            size_t off = ((size_t)(b * NH + h) * QLEN + q) * DH + d;
            float v = acc[i][j];
            if (sec == 0)      g_Qb[off] = v + rbias[h * 64 + d];
            else if (sec == 1) g_K[off] = v;
            else               g_V[off] = v;
        }
    }
}

// ---------------- GEMM 2: r_head_k = r @ r_net_w, scatter to Rk -------------
__global__ __launch_bounds__(256)
void gemm_rnet_kernel(const float* __restrict__ A, const float* __restrict__ B) {
    const int K = DM, N = NH * DH;  // 1024, 1024
    __shared__ float As[8][128];
    __shared__ float Bs[8][128];
    int tid = threadIdx.x;
    int tx = tid & 15, ty = tid >> 4;
    int row0 = blockIdx.y * 128, col0 = blockIdx.x * 128;
    float acc[8][8] = {};
    int ar = tid >> 1, ac = (tid & 1) * 4;
    int br = tid >> 5, bc = (tid & 31) * 4;
    for (int k0 = 0; k0 < K; k0 += 8) {
        float4 av = *(const float4*)&A[(size_t)(row0 + ar) * K + k0 + ac];
        As[ac + 0][ar] = av.x; As[ac + 1][ar] = av.y;
        As[ac + 2][ar] = av.z; As[ac + 3][ar] = av.w;
        *(float4*)&Bs[br][bc] = *(const float4*)&B[(size_t)(k0 + br) * N + col0 + bc];
        __syncthreads();
#pragma unroll
        for (int kk = 0; kk < 8; kk++) {
            float a[8], b[8];
#pragma unroll
            for (int i = 0; i < 8; i++) a[i] = As[kk][ty * 8 + i];
#pragma unroll
            for (int j = 0; j < 8; j++) b[j] = Bs[kk][tx * 8 + j];
#pragma unroll
            for (int i = 0; i < 8; i++)
#pragma unroll
                for (int j = 0; j < 8; j++) acc[i][j] += a[i] * b[j];
        }
        __syncthreads();
    }
#pragma unroll
    for (int i = 0; i < 8; i++) {
        int rr = row0 + ty * 8 + i;
#pragma unroll
        for (int j = 0; j < 8; j++) {
            int c = col0 + tx * 8 + j;
            int h = c >> 6, d = c & 63;
            g_Rk[((size_t)h * RLEN + rr) * DH + d] = acc[i][j];
        }
    }
}

// ---------------- GEMM 3 (NT): BD_raw[b,n] = Qb[b,n] @ Rk[n]^T ---------------
__global__ __launch_bounds__(256)
void gemm_bd_kernel() {
    int z = blockIdx.z;            // b*NH + n
    int n = z & (NH - 1);
    const float* A = g_Qb + (size_t)z * QLEN * DH;
    const float* Bm = g_Rk + (size_t)n * RLEN * DH;
    __shared__ float As[8][128];
    __shared__ float Bs[8][128];
    int tid = threadIdx.x;
    int tx = tid & 15, ty = tid >> 4;
    int row0 = blockIdx.y * 128, col0 = blockIdx.x * 128;
    float acc[8][8] = {};
    int ar = tid >> 1, ac = (tid & 1) * 4;
    for (int k0 = 0; k0 < DH; k0 += 8) {
        float4 av = *(const float4*)&A[(size_t)(row0 + ar) * DH + k0 + ac];
        As[ac + 0][ar] = av.x; As[ac + 1][ar] = av.y;
        As[ac + 2][ar] = av.z; As[ac + 3][ar] = av.w;
        float4 bv = *(const float4*)&Bm[(size_t)(col0 + ar) * DH + k0 + ac];
        Bs[ac + 0][ar] = bv.x; Bs[ac + 1][ar] = bv.y;
        Bs[ac + 2][ar] = bv.z; Bs[ac + 3][ar] = bv.w;
        __syncthreads();
#pragma unroll
        for (int kk = 0; kk < 8; kk++) {
            float a[8], b[8];
#pragma unroll
            for (int i = 0; i < 8; i++) a[i] = As[kk][ty * 8 + i];
#pragma unroll
            for (int j = 0; j < 8; j++) b[j] = Bs[kk][tx * 8 + j];
#pragma unroll
            for (int i = 0; i < 8; i++)
#pragma unroll
                for (int j = 0; j < 8; j++) acc[i][j] += a[i] * b[j];
        }
        __syncthreads();
    }
    float* C = g_BD + (size_t)z * QLEN * RLEN;
#pragma unroll
    for (int i = 0; i < 8; i++) {
        int q = row0 + ty * 8 + i;
#pragma unroll
        for (int j = 0; j < 8; j++) {
            int rr = col0 + tx * 8 + j;
            C[(size_t)q * RLEN + rr] = acc[i][j];
        }
    }
}

// ---------------- GEMM 4 (NT): scores = (Q@K^T + rel_shift(BD)) * scale, mask
__global__ __launch_bounds__(256)
void gemm_score_kernel(const void* __restrict__ mask, float* __restrict__ cov) {
    int z = blockIdx.z;            // b*NH + n
    int b = z >> 4;
    const float* A = g_Qb + (size_t)z * QLEN * DH;
    const float* Bm = g_K + (size_t)z * KLEN * DH;
    __shared__ float As[8][128];
    __shared__ float Bs[8][128];
    int tid = threadIdx.x;
    int tx = tid & 15, ty = tid >> 4;
    int row0 = blockIdx.y * 128, col0 = blockIdx.x * 128;
    float acc[8][8] = {};
    int ar = tid >> 1, ac = (tid & 1) * 4;
    for (int k0 = 0; k0 < DH; k0 += 8) {
        float4 av = *(const float4*)&A[(size_t)(row0 + ar) * DH + k0 + ac];
        As[ac + 0][ar] = av.x; As[ac + 1][ar] = av.y;
        As[ac + 2][ar] = av.z; As[ac + 3][ar] = av.w;
        float4 bv = *(const float4*)&Bm[(size_t)(col0 + ar) * DH + k0 + ac];
        Bs[ac + 0][ar] = bv.x; Bs[ac + 1][ar] = bv.y;
        Bs[ac + 2][ar] = bv.z; Bs[ac + 3][ar] = bv.w;
        __syncthreads();
#pragma unroll
        for (int kk = 0; kk < 8; kk++) {
            float a[8], bb[8];
#pragma unroll
            for (int i = 0; i < 8; i++) a[i] = As[kk][ty * 8 + i];
#pragma unroll
            for (int j = 0; j < 8; j++) bb[j] = Bs[kk][tx * 8 + j];
#pragma unroll
            for (int i = 0; i < 8; i++)
#pragma unroll
                for (int j = 0; j < 8; j++) acc[i][j] += a[i] * bb[j];
        }
        __syncthreads();
    }
    const float* BDz = g_BD + (size_t)z * QLEN * RLEN;
    float* Cz = cov + (size_t)z * QLEN * KLEN;
    int mode = g_mask_mode;
#pragma unroll
    for (int i = 0; i < 8; i++) {
        int q = row0 + ty * 8 + i;
#pragma unroll
        for (int j = 0; j < 8; j++) {
            int k = col0 + tx * 8 + j;
            // exact flat-index rel_shift (preserves the k>q "leak")
            int f = (q + 1) * RLEN + k;
            int ii = f / (RLEN + 1);
            int jj = f - ii * (RLEN + 1);
            float bd = (jj == 0) ? 0.0f : BDz[(size_t)ii * RLEN + (jj - 1)];
            float s = (acc[i][j] + bd) * SCALE;
            int midx = k * BSZ + b;
            bool msk;
            if (mode == 0)      msk = ((const int*)mask)[midx] != 0;
            else if (mode == 1) msk = ((const float*)mask)[midx] != 0.0f;
            else                msk = ((const unsigned char*)mask)[midx] != 0;
            Cz[(size_t)q * KLEN + k] = msk ? -INFINITY : s;
        }
    }
}

// ---------------- softmax over k, in place in coverage region ----------------
__global__ __launch_bounds__(256)
void softmax_kernel(float* __restrict__ cov) {
    size_t row = blockIdx.x;
    float* p = cov + row * KLEN;
    int t = threadIdx.x;
    float4 v0 = ((const float4*)p)[t];
    float4 v1 = ((const float4*)p)[t + 256];
    float m = fmaxf(fmaxf(fmaxf(v0.x, v0.y), fmaxf(v0.z, v0.w)),
                    fmaxf(fmaxf(v1.x, v1.y), fmaxf(v1.z, v1.w)));
    __shared__ float sred[8];
#pragma unroll
    for (int o = 16; o; o >>= 1) m = fmaxf(m, __shfl_xor_sync(0xffffffffu, m, o));
    if ((t & 31) == 0) sred[t >> 5] = m;
    __syncthreads();
    if (t < 8) {
        float x = sred[t];
#pragma unroll
        for (int o = 4; o; o >>= 1) x = fmaxf(x, __shfl_xor_sync(0xffu, x, o));
        if (t == 0) sred[0] = x;
    }
    __syncthreads();
    m = sred[0];
    if (m == -INFINITY) {   // fully-masked row -> softmax NaN -> 0 per reference
        float4 zz = make_float4(0.f, 0.f, 0.f, 0.f);
        ((float4*)p)[t] = zz;
        ((float4*)p)[t + 256] = zz;
        return;
    }
    float e0x = expf(v0.x - m), e0y = expf(v0.y - m), e0z = expf(v0.z - m), e0w = expf(v0.w - m);
    float e1x = expf(v1.x - m), e1y = expf(v1.y - m), e1z = expf(v1.z - m), e1w = expf(v1.w - m);
    float s = (e0x + e0y) + (e0z + e0w) + (e1x + e1y) + (e1z + e1w);
    __shared__ float ssum[8];
#pragma unroll
    for (int o = 16; o; o >>= 1) s += __shfl_xor_sync(0xffffffffu, s, o);
    if ((t & 31) == 0) ssum[t >> 5] = s;
    __syncthreads();
    if (t < 8) {
        float x = ssum[t];
#pragma unroll
        for (int o = 4; o; o >>= 1) x += __shfl_xor_sync(0xffu, x, o);
        if (t == 0) ssum[0] = x;
    }
    __syncthreads();
    float inv = 1.0f / ssum[0];
    float4 o0 = make_float4(e0x * inv, e0y * inv, e0z * inv, e0w * inv);
    float4 o1 = make_float4(e1x * inv, e1y * inv, e1z * inv, e1w * inv);
    ((float4*)p)[t] = o0;
    ((float4*)p)[t + 256] = o1;
}

// ---------------- GEMM 5: attn_vec[b,n] = P[b,n] @ V[b,n] -------------------
// per z: P (2048 x 2048) @ V (2048 x 64). BM=128, BN=64, BK=8, TM=8, TN=4.
__global__ __launch_bounds__(256)
void gemm_pv_kernel(const float* __restrict__ cov) {
    int z = blockIdx.y;            // b*NH + n
    int b = z >> 4, n = z & (NH - 1);
    const float* P = cov + (size_t)z * QLEN * KLEN;
    const float* Vm = g_V + (size_t)z * KLEN * DH;
    __shared__ float As[8][128];
    __shared__ float Bs[8][64];
    int tid = threadIdx.x;
    int tx = tid & 15, ty = tid >> 4;
    int row0 = blockIdx.x * 128;
    float acc[8][4] = {};
    int ar = tid >> 1, ac = (tid & 1) * 4;
    int br = tid >> 4, bc = (tid & 15) * 4;   // threads 0..127 load B
    for (int k0 = 0; k0 < KLEN; k0 += 8) {
        float4 av = *(const float4*)&P[(size_t)(row0 + ar) * KLEN + k0 + ac];
        As[ac + 0][ar] = av.x; As[ac + 1][ar] = av.y;
        As[ac + 2][ar] = av.z; As[ac + 3][ar] = av.w;
        if (tid < 128)
            *(float4*)&Bs[br][bc] = *(const float4*)&Vm[(size_t)(k0 + br) * DH + bc];
        __syncthreads();
#pragma unroll
        for (int kk = 0; kk < 8; kk++) {
            float a[8], bb[4];
#pragma unroll
            for (int i = 0; i < 8; i++) a[i] = As[kk][ty * 8 + i];
#pragma unroll
            for (int j = 0; j < 4; j++) bb[j] = Bs[kk][tx * 4 + j];
#pragma unroll
            for (int i = 0; i < 8; i++)
#pragma unroll
                for (int j = 0; j < 4; j++) acc[i][j] += a[i] * bb[j];
        }
        __syncthreads();
    }
#pragma unroll
    for (int i = 0; i < 8; i++) {
        int q = row0 + ty * 8 + i;
#pragma unroll
        for (int j = 0; j < 4; j++) {
            int d = tx * 4 + j;
            g_AV[((size_t)q * BSZ + b) * DM + n * DH + d] = acc[i][j];
        }
    }
}

// ---------------- GEMM 6: output = attn_vec @ o_w ---------------------------
__global__ __launch_bounds__(256)
void gemm_out_kernel(const float* __restrict__ B, float* __restrict__ out) {
    const int K = DM, N = DM;
    const float* A = g_AV;
    __shared__ float As[8][128];
    __shared__ float Bs[8][128];
    int tid = threadIdx.x;
    int tx = tid & 15, ty = tid >> 4;
    int row0 = blockIdx.y * 128, col0 = blockIdx.x * 128;
    float acc[8][8] = {};
    int ar = tid >> 1, ac = (tid & 1) * 4;
    int br = tid >> 5, bc = (tid & 31) * 4;
    for (int k0 = 0; k0 < K; k0 += 8) {
        float4 av = *(const float4*)&A[(size_t)(row0 + ar) * K + k0 + ac];
        As[ac + 0][ar] = av.x; As[ac + 1][ar] = av.y;
        As[ac + 2][ar] = av.z; As[ac + 3][ar] = av.w;
        *(float4*)&Bs[br][bc] = *(const float4*)&B[(size_t)(k0 + br) * N + col0 + bc];
        __syncthreads();
#pragma unroll
        for (int kk = 0; kk < 8; kk++) {
            float a[8], b[8];
#pragma unroll
            for (int i = 0; i < 8; i++) a[i] = As[kk][ty * 8 + i];
#pragma unroll
            for (int j = 0; j < 8; j++) b[j] = Bs[kk][tx * 8 + j];
#pragma unroll
            for (int i = 0; i < 8; i++)
#pragma unroll
                for (int j = 0; j < 8; j++) acc[i][j] += a[i] * b[j];
        }
        __syncthreads();
    }
#pragma unroll
    for (int i = 0; i < 8; i++) {
        int m = row0 + ty * 8 + i;
#pragma unroll
        for (int j = 0; j < 8; j++) {
            int c = col0 + tx * 8 + j;
            out[(size_t)m * N + c] = acc[i][j];
        }
    }
}

// ---------------- launch ------------------------------------------------------
extern "C" void kernel_launch(void* const* d_in, const int* in_sizes, int n_in,
                              void* d_out, int out_size) {
    const float* w       = (const float*)d_in[0];  // (2048, 2, 1024)
    const float* r       = (const float*)d_in[1];  // (2048, 1024)
    const void*  mask    = d_in[2];                // (2048, 2) bool-ish
    const float* qkv_w   = (const float*)d_in[3];  // (1024, 3072)
    const float* r_net_w = (const float*)d_in[4];  // (1024, 1024)
    const float* o_w     = (const float*)d_in[5];  // (1024, 1024)
    // d_in[6] = r_w_bias: unused (reference bug uses r_r_bias for both)
    const float* r_r_bias = (const float*)d_in[7]; // (16, 64)

    float* out = (float*)d_out;                             // first 4,194,304 floats
    float* cov = out + (size_t)QLEN * BSZ * DM;             // coverage: 2*16*2048*2048

    detect_mask_kernel<<<1, 256>>>((const unsigned char*)mask);
    gemm_qkv_kernel<<<dim3(24, 32), 256>>>(w, qkv_w, r_r_bias);
    gemm_rnet_kernel<<<dim3(8, 16), 256>>>(r, r_net_w);
    gemm_bd_kernel<<<dim3(16, 16, BSZ * NH), 256>>>();
    gemm_score_kernel<<<dim3(16, 16, BSZ * NH), 256>>>(mask, cov);
    softmax_kernel<<<BSZ * NH * QLEN, 256>>>(cov);
    gemm_pv_kernel<<<dim3(16, BSZ * NH), 256>>>(cov);
    gemm_out_kernel<<<dim3(8, 32), 256>>>(o_w, out);
}